// round 13
// baseline (speedup 1.0000x reference)
#include <cuda_runtime.h>
#include <cstdint>

#define NT 1000000
#define NC 500000
#define NM 100000

// ---------------- scratch (static device globals; no allocation) ----------------
__device__ float g_ht[NT * 16];       // layer-0 txn self-projection
__device__ float g_ht2[NT * 16];      // layer-1 txn self-projection (no in-place aliasing)
__device__ float g_bufcA[NC * 16];    // card proj, layers 0 and 2
__device__ float g_bufmA[NM * 16];
__device__ float g_bufcB[NC * 16];    // card proj, layer 1
__device__ float g_bufmB[NM * 16];
__device__ float g_sumcA[NC * 16];    // layer-0 message sums
__device__ float g_summA[NM * 16];
__device__ float g_sumcB[NC * 16];    // layer-1 message sums
__device__ float g_summB[NM * 16];
__device__ float g_cntc[NC];
__device__ float g_cntm[NM];

#define GT_BLK 3907    // ceil(NT/256)
#define NODE_BLK 2344  // ceil((NC+NM)/256)
#define TXN1_BLK 7813  // ceil(NT/128)

// mega0 128-row blocks
#define GC0 3907       // ceil(NC/128)
#define GM0 782        // ceil(NM/128)
#define GT0 7813       // ceil(NT/128)

__device__ __forceinline__ float lrelu_f(float v) { return v > 0.f ? v : 0.01f * v; }

__device__ __forceinline__ void red4(float* p, float a, float b, float c, float d) {
    asm volatile("red.global.add.v4.f32 [%0], {%1,%2,%3,%4};"
                 :: "l"(p), "f"(a), "f"(b), "f"(c), "f"(d) : "memory");
}
__device__ __forceinline__ void red1(float* p, float a) {
    asm volatile("red.global.add.f32 [%0], %1;" :: "l"(p), "f"(a) : "memory");
}

__device__ __forceinline__ uint32_t f2tf32(float f) {
    uint32_t r; asm("cvt.rna.tf32.f32 %0, %1;" : "=r"(r) : "f"(f)); return r;
}

__device__ __forceinline__ void mma_tf32(float& d0, float& d1, float& d2, float& d3,
                                         uint32_t a0, uint32_t a1, uint32_t a2, uint32_t a3,
                                         uint32_t b0, uint32_t b1) {
    asm volatile("mma.sync.aligned.m16n8k8.row.col.f32.tf32.tf32.f32 "
                 "{%0,%1,%2,%3}, {%4,%5,%6,%7}, {%8,%9}, {%0,%1,%2,%3};"
                 : "+f"(d0), "+f"(d1), "+f"(d2), "+f"(d3)
                 : "r"(a0), "r"(a1), "r"(a2), "r"(a3), "r"(b0), "r"(b1));
}

__device__ __forceinline__ void cp_async16(void* dst_smem, const void* src, bool pred) {
    uint32_t d = (uint32_t)__cvta_generic_to_shared(dst_smem);
    asm volatile("cp.async.cg.shared.global [%0], [%1], 16, %2;"
                 :: "r"(d), "l"(src), "r"(pred ? 16 : 0));
}
#define CP_COMMIT() asm volatile("cp.async.commit_group;")
#define CP_WAIT2()  asm volatile("cp.async.wait_group 2;")

// ---------------- zero kernels (split so mega0 is the 4th launch for ncu) ----------------
__global__ void zeroA_kernel() {
    const int a1 = 2000000, a2 = a1 + 400000;
    const float4 z = make_float4(0.f, 0.f, 0.f, 0.f);
    for (int i = blockIdx.x * blockDim.x + threadIdx.x; i < a2; i += gridDim.x * blockDim.x) {
        if (i < a1) ((float4*)g_sumcA)[i] = z;
        else        ((float4*)g_summA)[i - a1] = z;
    }
}
__global__ void zeroB_kernel() {
    const int a1 = 2000000, a2 = a1 + 400000;
    const float4 z = make_float4(0.f, 0.f, 0.f, 0.f);
    for (int i = blockIdx.x * blockDim.x + threadIdx.x; i < a2; i += gridDim.x * blockDim.x) {
        if (i < a1) ((float4*)g_sumcB)[i] = z;
        else        ((float4*)g_summB)[i - a1] = z;
    }
}
__global__ void zeroC_kernel() {
    const int a1 = 125000, a2 = a1 + 25000;
    const float4 z = make_float4(0.f, 0.f, 0.f, 0.f);
    for (int i = blockIdx.x * blockDim.x + threadIdx.x; i < a2; i += gridDim.x * blockDim.x) {
        if (i < a1) ((float4*)g_cntc)[i] = z;
        else        ((float4*)g_cntm)[i - a1] = z;
    }
}

// ================= TF32 MMA mainloop, 128-row block, K=128, 4-stage depth-3 =================
// smem layout (dynamic, 70848 bytes):
//   [0, 40960)       float Xs[4][128][20]   (reused as Cs[128][52] post-loop)
//   [40960, 69632)   uint32_t Ws[128][56]
//   [69632, 69824)   float bs[48]
//   [69824, 70336)   int ciS[128]
//   [70336, 70848)   int miS[128]
#define M0_SMEM 70848

template <int NTILES>
__device__ __forceinline__ void mma_loop_128(const float* __restrict__ X, int nrows, int row0,
                                             const float* __restrict__ Wg,
                                             char* smem, float c[NTILES][4]) {
    float(*Xs)[20] = (float(*)[20])smem;
    uint32_t(*Ws)[56] = (uint32_t(*)[56])(smem + 40960);
    const int tid = threadIdx.x;
    const int lane = tid & 31, wid = tid >> 5;
    const int gid = lane >> 2, tig = lane & 3;

    for (int i = tid; i < 128 * NTILES * 8; i += 256) {
        int k = i / (NTILES * 8), cc = i % (NTILES * 8);
        Ws[k][cc] = f2tf32(Wg[(cc >> 4) * 2048 + k * 16 + (cc & 15)]);
    }

#pragma unroll
    for (int nt = 0; nt < NTILES; nt++)
#pragma unroll
        for (int q = 0; q < 4; q++) c[nt][q] = 0.f;

    auto prefetch = [&](int ch) {
        int st = ch & 3;
#pragma unroll
        for (int j = 0; j < 2; j++) {
            int idx = tid + j * 256;
            int r = idx >> 2, p = idx & 3;
            int row = row0 + r;
            bool ok = row < nrows;
            const float* src = X + (size_t)(ok ? row : 0) * 128 + ch * 16 + p * 4;
            cp_async16(&Xs[st * 128 + r][p * 4], src, ok);
        }
    };
    prefetch(0); CP_COMMIT();
    prefetch(1); CP_COMMIT();
    prefetch(2); CP_COMMIT();

    for (int ch = 0; ch < 8; ch++) {
        CP_WAIT2();
        __syncthreads();
        if (ch + 3 < 8) prefetch(ch + 3);
        CP_COMMIT();
        const float(*xb)[20] = Xs + (ch & 3) * 128;
        const int rb = wid * 16;
#pragma unroll
        for (int ks = 0; ks < 2; ks++) {
            int k0 = ks * 8, kk = ch * 16 + k0;
            uint32_t a0 = f2tf32(xb[rb + gid][k0 + tig]);
            uint32_t a1 = f2tf32(xb[rb + 8 + gid][k0 + tig]);
            uint32_t a2 = f2tf32(xb[rb + gid][k0 + tig + 4]);
            uint32_t a3 = f2tf32(xb[rb + 8 + gid][k0 + tig + 4]);
#pragma unroll
            for (int nt = 0; nt < NTILES; nt++) {
                uint32_t b0 = Ws[kk + tig][nt * 8 + gid];
                uint32_t b1 = Ws[kk + tig + 4][nt * 8 + gid];
                mma_tf32(c[nt][0], c[nt][1], c[nt][2], c[nt][3], a0, a1, a2, a3, b0, b1);
            }
        }
    }
}

// ================= mega0: all three layer-0 projections + counts (128-row blocks) =================
__global__ __launch_bounds__(256, 3) void mega0(const float* __restrict__ feats,
                                                const float* __restrict__ emb_card,
                                                const float* __restrict__ emb_merch,
                                                const float* __restrict__ W0,
                                                const float* __restrict__ b0,
                                                const int* __restrict__ ci,
                                                const int* __restrict__ mi) {
    extern __shared__ __align__(16) char smem[];
    float* bs = (float*)(smem + 69632);
    int* ciS = (int*)(smem + 69824);
    int* miS = (int*)(smem + 70336);
    const int tid = threadIdx.x, lane = tid & 31, wid = tid >> 5;
    const int gid = lane >> 2, tig = lane & 3;
    int b = blockIdx.x;

    if (b < GC0 + GM0) {
        // ---- node projection role (card / merchant) ----
        bool isM = b >= GC0;
        int row0 = (isM ? (b - GC0) : b) * 128;
        int nrows = isM ? NM : NC;
        const float* X = isM ? emb_merch : emb_card;
        const float* Wg = W0 + (isM ? 2048 : 0);
        const float* B = b0 + (isM ? 16 : 0);
        float* out = isM ? g_bufmA : g_bufcA;
        if (tid < 16) bs[tid] = B[tid];
        float c[2][4];
        mma_loop_128<2>(X, nrows, row0, Wg, smem, c);
#pragma unroll
        for (int nt = 0; nt < 2; nt++) {
            int col = nt * 8 + 2 * tig;
            int r0_ = row0 + wid * 16 + gid, r1_ = r0_ + 8;
            float bx = bs[col], by = bs[col + 1];
            if (r0_ < nrows)
                *(float2*)(out + (size_t)r0_ * 16 + col) =
                    make_float2(c[nt][0] + bx, c[nt][1] + by);
            if (r1_ < nrows)
                *(float2*)(out + (size_t)r1_ * 16 + col) =
                    make_float2(c[nt][2] + bx, c[nt][3] + by);
        }
    } else {
        // ---- txn role: feats @ W0[2..4]; self -> g_ht, scatter -> sumsA, counts ----
        int row0 = (b - GC0 - GM0) * 128;
        if (tid < 48) bs[tid] = b0[32 + tid];
        if (tid < 128) {
            int row = row0 + tid;
            ciS[tid] = (row < NT) ? ci[row] : 0;
            miS[tid] = (row < NT) ? mi[row] : 0;
        }
        float c[6][4];
        mma_loop_128<6>(feats, NT, row0, W0 + 4096, smem, c);

        __syncthreads();                      // Xs dead; reuse as Cs[128][52]
        float* Cs = (float*)smem;
#pragma unroll
        for (int nt = 0; nt < 6; nt++) {
            int ra = wid * 16 + gid, rb = ra + 8, col = nt * 8 + 2 * tig;
            *(float2*)(Cs + ra * 52 + col) = make_float2(c[nt][0], c[nt][1]);
            *(float2*)(Cs + rb * 52 + col) = make_float2(c[nt][2], c[nt][3]);
        }
        __syncthreads();

        const int cg = tid & 3, rg = tid >> 2;
#pragma unroll
        for (int pass = 0; pass < 2; pass++) {
            int r = pass * 64 + rg, row = row0 + r;
            if (row < NT) {
                int cI = ciS[r], mI = miS[r];
#pragma unroll
                for (int u = 0; u < 3; u++) {
                    int q = cg * 12 + u * 4;
                    float4 v = *(const float4*)(Cs + r * 52 + q);
                    float vx = v.x + bs[q + 0], vy = v.y + bs[q + 1];
                    float vz = v.z + bs[q + 2], vw = v.w + bs[q + 3];
                    int e = q >> 4, j = q & 15;
                    if (e == 0)
                        *(float4*)(g_ht + (size_t)row * 16 + j) = make_float4(vx, vy, vz, vw);
                    else if (e == 1) {
                        red4(&g_sumcA[(size_t)cI * 16 + j], vx, vy, vz, vw);
                        if (q == 16) red1(&g_cntc[cI], 1.f);
                    } else {
                        red4(&g_summA[(size_t)mI * 16 + j], vx, vy, vz, vw);
                        if (q == 32) red1(&g_cntm[mI], 1.f);
                    }
                }
            }
        }
    }
}

// ================= mega1 (per-row): node + txn roles =================
__global__ __launch_bounds__(256) void mega1(const float* __restrict__ W1,
                                             const float* __restrict__ b1,
                                             const int* __restrict__ ci,
                                             const int* __restrict__ mi) {
    __shared__ float Ws[768];
    __shared__ float bs[48];
    const int tid = threadIdx.x;
    int b = blockIdx.x;

    if (b < NODE_BLK) {
        for (int i = tid; i < 512; i += 256) Ws[i] = W1[i];
        if (tid < 32) bs[tid] = b1[tid];
        __syncthreads();

        int gr = b * 256 + tid;
        if (gr < NC + NM) {
            bool isM = gr >= NC;
            int row = isM ? gr - NC : gr;
            const float4* S4 = (const float4*)(isM ? g_summA : g_sumcA);
            const float* cnt = isM ? g_cntm : g_cntc;
            float* out = isM ? g_bufmB : g_bufcB;
            const float* w = Ws + (isM ? 256 : 0);
            const float* bb = bs + (isM ? 16 : 0);

            float4 s0 = S4[(size_t)row * 4 + 0];
            float4 s1 = S4[(size_t)row * 4 + 1];
            float4 s2 = S4[(size_t)row * 4 + 2];
            float4 s3 = S4[(size_t)row * 4 + 3];
            float inv = 1.f / fmaxf(cnt[row], 1.f);
            float x[16] = {lrelu_f(s0.x * inv), lrelu_f(s0.y * inv), lrelu_f(s0.z * inv), lrelu_f(s0.w * inv),
                           lrelu_f(s1.x * inv), lrelu_f(s1.y * inv), lrelu_f(s1.z * inv), lrelu_f(s1.w * inv),
                           lrelu_f(s2.x * inv), lrelu_f(s2.y * inv), lrelu_f(s2.z * inv), lrelu_f(s2.w * inv),
                           lrelu_f(s3.x * inv), lrelu_f(s3.y * inv), lrelu_f(s3.z * inv), lrelu_f(s3.w * inv)};
            float acc[16];
#pragma unroll
            for (int c = 0; c < 16; c++) acc[c] = 0.f;
#pragma unroll
            for (int k = 0; k < 16; k++) {
                float xk = x[k];
#pragma unroll
                for (int c = 0; c < 16; c++) acc[c] += xk * w[k * 16 + c];
            }
#pragma unroll
            for (int p = 0; p < 4; p++)
                *(float4*)(out + (size_t)row * 16 + p * 4) =
                    make_float4(acc[p * 4 + 0] + bb[p * 4 + 0], acc[p * 4 + 1] + bb[p * 4 + 1],
                                acc[p * 4 + 2] + bb[p * 4 + 2], acc[p * 4 + 3] + bb[p * 4 + 3]);
        }
    } else {
        for (int i = tid; i < 768; i += 256) {
            int k = i / 48, cc = i % 48;
            Ws[i] = W1[512 + (cc >> 4) * 256 + k * 16 + (cc & 15)];
        }
        if (tid < 48) bs[tid] = b1[32 + tid];
        __syncthreads();

        int half = tid & 1;             // SAME-warp split: lanes 2r, 2r+1 share one row
        int r = tid >> 1;
        int row = (b - NODE_BLK) * 128 + r;
        if (row < NT) {
            int cI = ci[row], mI = mi[row];
            const float4* ht4 = (const float4*)g_ht;
            const float4* bc4 = (const float4*)g_bufcA;
            const float4* bm4 = (const float4*)g_bufmA;
            float x[16];
#pragma unroll
            for (int p = 0; p < 4; p++) {
                float4 a = ht4[(size_t)row * 4 + p];
                float4 gc = bc4[(size_t)cI * 4 + p];
                float4 gm = bm4[(size_t)mI * 4 + p];
                x[p * 4 + 0] = lrelu_f(a.x + gc.x + gm.x);
                x[p * 4 + 1] = lrelu_f(a.y + gc.y + gm.y);
                x[p * 4 + 2] = lrelu_f(a.z + gc.z + gm.z);
                x[p * 4 + 3] = lrelu_f(a.w + gc.w + gm.w);
            }
            int c0 = half * 24;
            float acc[24];
#pragma unroll
            for (int c = 0; c < 24; c++) acc[c] = 0.f;
#pragma unroll
            for (int k = 0; k < 16; k++) {
                float xk = x[k];
#pragma unroll
                for (int c = 0; c < 24; c++) acc[c] += xk * Ws[k * 48 + c0 + c];
            }
#pragma unroll
            for (int c = 0; c < 24; c++) acc[c] += bs[c0 + c];

            if (half == 0) {
#pragma unroll
                for (int p = 0; p < 4; p++)
                    *(float4*)(g_ht2 + (size_t)row * 16 + p * 4) =
                        make_float4(acc[p * 4], acc[p * 4 + 1], acc[p * 4 + 2], acc[p * 4 + 3]);
                red4(&g_sumcB[(size_t)cI * 16 + 0], acc[16], acc[17], acc[18], acc[19]);
                red4(&g_sumcB[(size_t)cI * 16 + 4], acc[20], acc[21], acc[22], acc[23]);
            } else {
                red4(&g_sumcB[(size_t)cI * 16 + 8], acc[0], acc[1], acc[2], acc[3]);
                red4(&g_sumcB[(size_t)cI * 16 + 12], acc[4], acc[5], acc[6], acc[7]);
                red4(&g_summB[(size_t)mI * 16 + 0], acc[8], acc[9], acc[10], acc[11]);
                red4(&g_summB[(size_t)mI * 16 + 4], acc[12], acc[13], acc[14], acc[15]);
                red4(&g_summB[(size_t)mI * 16 + 8], acc[16], acc[17], acc[18], acc[19]);
                red4(&g_summB[(size_t)mI * 16 + 12], acc[20], acc[21], acc[22], acc[23]);
            }
        }
    }
}

// ================= mega2 (per-row): layer-2 card/merch projections (reads sumB) =================
__global__ __launch_bounds__(256) void mega2(const float* __restrict__ W2,
                                             const float* __restrict__ b2) {
    __shared__ float Ws[512];
    __shared__ float bs[32];
    const int tid = threadIdx.x;
    for (int i = tid; i < 512; i += 256) Ws[i] = W2[i];
    if (tid < 32) bs[tid] = b2[tid];
    __syncthreads();

    int gr = blockIdx.x * 256 + tid;
    if (gr >= NC + NM) return;
    bool isM = gr >= NC;
    int row = isM ? gr - NC : gr;
    const float4* S4 = (const float4*)(isM ? g_summB : g_sumcB);
    const float* cnt = isM ? g_cntm : g_cntc;
    float* out = isM ? g_bufmA : g_bufcA;
    const float* w = Ws + (isM ? 256 : 0);
    const float* bb = bs + (isM ? 16 : 0);

    float4 s0 = S4[(size_t)row * 4 + 0];
    float4 s1 = S4[(size_t)row * 4 + 1];
    float4 s2 = S4[(size_t)row * 4 + 2];
    float4 s3 = S4[(size_t)row * 4 + 3];
    float inv = 1.f / fmaxf(cnt[row], 1.f);
    float x[16] = {lrelu_f(s0.x * inv), lrelu_f(s0.y * inv), lrelu_f(s0.z * inv), lrelu_f(s0.w * inv),
                   lrelu_f(s1.x * inv), lrelu_f(s1.y * inv), lrelu_f(s1.z * inv), lrelu_f(s1.w * inv),
                   lrelu_f(s2.x * inv), lrelu_f(s2.y * inv), lrelu_f(s2.z * inv), lrelu_f(s2.w * inv),
                   lrelu_f(s3.x * inv), lrelu_f(s3.y * inv), lrelu_f(s3.z * inv), lrelu_f(s3.w * inv)};
    float acc[16];
#pragma unroll
    for (int c = 0; c < 16; c++) acc[c] = 0.f;
#pragma unroll
    for (int k = 0; k < 16; k++) {
        float xk = x[k];
#pragma unroll
        for (int c = 0; c < 16; c++) acc[c] += xk * w[k * 16 + c];
    }
#pragma unroll
    for (int p = 0; p < 4; p++)
        *(float4*)(out + (size_t)row * 16 + p * 4) =
            make_float4(acc[p * 4 + 0] + bb[p * 4 + 0], acc[p * 4 + 1] + bb[p * 4 + 1],
                        acc[p * 4 + 2] + bb[p * 4 + 2], acc[p * 4 + 3] + bb[p * 4 + 3]);
}

// ================= ka_out (per-row) =================
__global__ __launch_bounds__(256) void ka_out_kernel(const float* __restrict__ W,
                                                     const float* __restrict__ B,
                                                     const int* __restrict__ ci,
                                                     const int* __restrict__ mi,
                                                     const float* __restrict__ Wout,
                                                     const float* __restrict__ Bout,
                                                     float* __restrict__ out) {
    __shared__ float Ws[256];
    __shared__ float bs[16];
    __shared__ float wo[32];
    const int tid = threadIdx.x;
    if (tid < 256) Ws[tid] = W[tid];
    if (tid < 16) bs[tid] = B[tid];
    if (tid < 32) wo[tid] = Wout[tid];
    __syncthreads();

    int row = blockIdx.x * 256 + tid;
    if (row >= NT) return;
    int cI = ci[row], mI = mi[row];

    const float4* ht4 = (const float4*)g_ht2;
    const float4* bcB = (const float4*)g_bufcB;
    const float4* bmB = (const float4*)g_bufmB;
    float x[16];
#pragma unroll
    for (int p = 0; p < 4; p++) {
        float4 a = ht4[(size_t)row * 4 + p];
        float4 gc = bcB[(size_t)cI * 4 + p];
        float4 gm = bmB[(size_t)mI * 4 + p];
        x[p * 4 + 0] = lrelu_f(a.x + gc.x + gm.x);
        x[p * 4 + 1] = lrelu_f(a.y + gc.y + gm.y);
        x[p * 4 + 2] = lrelu_f(a.z + gc.z + gm.z);
        x[p * 4 + 3] = lrelu_f(a.w + gc.w + gm.w);
    }
    float acc[16];
#pragma unroll
    for (int c = 0; c < 16; c++) acc[c] = 0.f;
#pragma unroll
    for (int k = 0; k < 16; k++) {
        float xk = x[k];
#pragma unroll
        for (int c = 0; c < 16; c++) acc[c] += xk * Ws[k * 16 + c];
    }

    const float4* bcA = (const float4*)g_bufcA;
    const float4* bmA = (const float4*)g_bufmA;
    float o0 = 0.f, o1 = 0.f;
#pragma unroll
    for (int p = 0; p < 4; p++) {
        float4 gc = bcA[(size_t)cI * 4 + p];
        float4 gm = bmA[(size_t)mI * 4 + p];
        float h0 = acc[p * 4 + 0] + bs[p * 4 + 0] + gc.x + gm.x;
        float h1 = acc[p * 4 + 1] + bs[p * 4 + 1] + gc.y + gm.y;
        float h2 = acc[p * 4 + 2] + bs[p * 4 + 2] + gc.z + gm.z;
        float h3 = acc[p * 4 + 3] + bs[p * 4 + 3] + gc.w + gm.w;
        o0 += h0 * wo[(p * 4 + 0) * 2] + h1 * wo[(p * 4 + 1) * 2]
            + h2 * wo[(p * 4 + 2) * 2] + h3 * wo[(p * 4 + 3) * 2];
        o1 += h0 * wo[(p * 4 + 0) * 2 + 1] + h1 * wo[(p * 4 + 1) * 2 + 1]
            + h2 * wo[(p * 4 + 2) * 2 + 1] + h3 * wo[(p * 4 + 3) * 2 + 1];
    }
    *(float2*)(out + (size_t)row * 2) = make_float2(o0 + Bout[0], o1 + Bout[1]);
}

// ---------------- launcher (mega0 is the 4th launch -> ncu capture slot) ----------------
extern "C" void kernel_launch(void* const* d_in, const int* in_sizes, int n_in,
                              void* d_out, int out_size) {
    (void)in_sizes; (void)n_in; (void)out_size;
    const float* feats     = (const float*)d_in[0];
    const float* emb_card  = (const float*)d_in[1];
    const float* emb_merch = (const float*)d_in[2];
    const float* W0        = (const float*)d_in[3];
    const float* b0        = (const float*)d_in[4];
    const float* W1        = (const float*)d_in[5];
    const float* b1        = (const float*)d_in[6];
    const float* W2        = (const float*)d_in[7];
    const float* b2        = (const float*)d_in[8];
    const float* Wout      = (const float*)d_in[9];
    const float* bout      = (const float*)d_in[10];
    const int*   ci        = (const int*)d_in[11];
    const int*   mi        = (const int*)d_in[12];
    float* out = (float*)d_out;

    const int G0_ALL = GC0 + GM0 + GT0;   // 12502

    static bool attr_set = false;
    if (!attr_set) {
        cudaFuncSetAttribute(mega0, cudaFuncAttributeMaxDynamicSharedMemorySize, M0_SMEM);
        attr_set = true;
    }

    zeroA_kernel<<<2048, 256>>>();                                                 // 1
    zeroB_kernel<<<2048, 256>>>();                                                 // 2
    zeroC_kernel<<<586, 256>>>();                                                  // 3
    mega0<<<G0_ALL, 256, M0_SMEM>>>(feats, emb_card, emb_merch, W0, b0, ci, mi);   // 4 <- ncu
    mega1<<<NODE_BLK + TXN1_BLK, 256>>>(W1, b1, ci, mi);
    mega2<<<NODE_BLK, 256>>>(W2, b2);
    ka_out_kernel<<<GT_BLK, 256>>>(W2 + 512, b2 + 32, ci, mi, Wout, bout, out);
}

// round 14
// speedup vs baseline: 1.0524x; 1.0524x over previous
#include <cuda_runtime.h>
#include <cstdint>

#define NT 1000000
#define NC 500000
#define NM 100000

// ---------------- scratch (static device globals; no allocation) ----------------
__device__ float g_ht[NT * 16];       // layer-0 txn self-projection
__device__ float g_ht2[NT * 16];      // layer-1 txn self-projection (no in-place aliasing)
__device__ float g_bufcA[NC * 16];    // card proj, layers 0 and 2
__device__ float g_bufmA[NM * 16];
__device__ float g_bufcB[NC * 16];    // card proj, layer 1
__device__ float g_bufmB[NM * 16];
__device__ float g_sumcA[NC * 16];    // layer-0 message sums
__device__ float g_summA[NM * 16];
__device__ float g_sumcB[NC * 16];    // layer-1 message sums
__device__ float g_summB[NM * 16];
__device__ float g_cntc[NC];
__device__ float g_cntm[NM];

#define GC_BLK 1954    // ceil(NC/256)
#define GM_BLK 391     // ceil(NM/256)
#define GT_BLK 3907    // ceil(NT/256)
#define NODE_BLK 2344  // ceil((NC+NM)/256)
#define TXN1_BLK 7813  // ceil(NT/128)

__device__ __forceinline__ float lrelu_f(float v) { return v > 0.f ? v : 0.01f * v; }

__device__ __forceinline__ void red4(float* p, float a, float b, float c, float d) {
    asm volatile("red.global.add.v4.f32 [%0], {%1,%2,%3,%4};"
                 :: "l"(p), "f"(a), "f"(b), "f"(c), "f"(d) : "memory");
}
__device__ __forceinline__ void red1(float* p, float a) {
    asm volatile("red.global.add.f32 [%0], %1;" :: "l"(p), "f"(a) : "memory");
}

__device__ __forceinline__ uint32_t f2tf32(float f) {
    uint32_t r; asm("cvt.rna.tf32.f32 %0, %1;" : "=r"(r) : "f"(f)); return r;
}

__device__ __forceinline__ void mma_tf32(float& d0, float& d1, float& d2, float& d3,
                                         uint32_t a0, uint32_t a1, uint32_t a2, uint32_t a3,
                                         uint32_t b0, uint32_t b1) {
    asm volatile("mma.sync.aligned.m16n8k8.row.col.f32.tf32.tf32.f32 "
                 "{%0,%1,%2,%3}, {%4,%5,%6,%7}, {%8,%9}, {%0,%1,%2,%3};"
                 : "+f"(d0), "+f"(d1), "+f"(d2), "+f"(d3)
                 : "r"(a0), "r"(a1), "r"(a2), "r"(a3), "r"(b0), "r"(b1));
}

__device__ __forceinline__ void cp_async16(void* dst_smem, const void* src, bool pred) {
    uint32_t d = (uint32_t)__cvta_generic_to_shared(dst_smem);
    asm volatile("cp.async.cg.shared.global [%0], [%1], 16, %2;"
                 :: "r"(d), "l"(src), "r"(pred ? 16 : 0));
}
#define CP_COMMIT() asm volatile("cp.async.commit_group;")
#define CP_WAIT2()  asm volatile("cp.async.wait_group 2;")

// ---------------- zero kernels (order: zeroA, zeroBC, mega0, mega1 <- ncu 4th slot) ----------------
__global__ void zeroA_kernel() {           // sumcA + summA : 2.4M float4
    const int a1 = 2000000, a2 = a1 + 400000;
    const float4 z = make_float4(0.f, 0.f, 0.f, 0.f);
    for (int i = blockIdx.x * blockDim.x + threadIdx.x; i < a2; i += gridDim.x * blockDim.x) {
        if (i < a1) ((float4*)g_sumcA)[i] = z;
        else        ((float4*)g_summA)[i - a1] = z;
    }
}
__global__ void zeroBC_kernel() {          // sumcB + summB + cntc + cntm
    const int a1 = 2000000, a2 = a1 + 400000, a3 = a2 + 125000, a4 = a3 + 25000;
    const float4 z = make_float4(0.f, 0.f, 0.f, 0.f);
    for (int i = blockIdx.x * blockDim.x + threadIdx.x; i < a4; i += gridDim.x * blockDim.x) {
        if (i < a1)      ((float4*)g_sumcB)[i] = z;
        else if (i < a2) ((float4*)g_summB)[i - a1] = z;
        else if (i < a3) ((float4*)g_cntc)[i - a2] = z;
        else             ((float4*)g_cntm)[i - a3] = z;
    }
}

// ================= TF32 MMA mainloop, 256-row block, K=128, 4-stage depth-3 (R11 config) =================
// smem layout (dynamic, 112832 bytes):
//   [0, 81920)        float Xs[4][256][20]    (reused as Cs[256][52] post-loop)
//   [81920, 110592)   uint32_t Ws[128][56]
//   [110592, 110784)  float bs[48]
//   [110784, 111808)  int ciS[256]
//   [111808, 112832)  int miS[256]
#define M0_SMEM 112832

template <int NTILES>
__device__ __forceinline__ void mma_loop_256(const float* __restrict__ X, int nrows, int row0,
                                             const float* __restrict__ Wg,
                                             char* smem, float c[2][NTILES][4]) {
    float(*Xs)[20] = (float(*)[20])smem;
    uint32_t(*Ws)[56] = (uint32_t(*)[56])(smem + 81920);
    const int tid = threadIdx.x;
    const int lane = tid & 31, wid = tid >> 5;
    const int gid = lane >> 2, tig = lane & 3;

    for (int i = tid; i < 128 * NTILES * 8; i += 256) {
        int k = i / (NTILES * 8), cc = i % (NTILES * 8);
        Ws[k][cc] = f2tf32(Wg[(cc >> 4) * 2048 + k * 16 + (cc & 15)]);
    }

#pragma unroll
    for (int mt = 0; mt < 2; mt++)
#pragma unroll
        for (int nt = 0; nt < NTILES; nt++)
#pragma unroll
            for (int q = 0; q < 4; q++) c[mt][nt][q] = 0.f;

    auto prefetch = [&](int ch) {
        int st = ch & 3;
#pragma unroll
        for (int j = 0; j < 4; j++) {
            int idx = tid + j * 256;
            int r = idx >> 2, p = idx & 3;
            int row = row0 + r;
            bool ok = row < nrows;
            const float* src = X + (size_t)(ok ? row : 0) * 128 + ch * 16 + p * 4;
            cp_async16(&Xs[st * 256 + r][p * 4], src, ok);
        }
    };
    prefetch(0); CP_COMMIT();
    prefetch(1); CP_COMMIT();
    prefetch(2); CP_COMMIT();

    for (int ch = 0; ch < 8; ch++) {
        CP_WAIT2();
        __syncthreads();
        if (ch + 3 < 8) prefetch(ch + 3);
        CP_COMMIT();
        const float(*xb)[20] = Xs + (ch & 3) * 256;
#pragma unroll
        for (int ks = 0; ks < 2; ks++) {
            int k0 = ks * 8, kk = ch * 16 + k0;
#pragma unroll
            for (int mt = 0; mt < 2; mt++) {
                int rb = wid * 32 + mt * 16;
                uint32_t a0 = f2tf32(xb[rb + gid][k0 + tig]);
                uint32_t a1 = f2tf32(xb[rb + 8 + gid][k0 + tig]);
                uint32_t a2 = f2tf32(xb[rb + gid][k0 + tig + 4]);
                uint32_t a3 = f2tf32(xb[rb + 8 + gid][k0 + tig + 4]);
#pragma unroll
                for (int nt = 0; nt < NTILES; nt++) {
                    uint32_t b0 = Ws[kk + tig][nt * 8 + gid];
                    uint32_t b1 = Ws[kk + tig + 4][nt * 8 + gid];
                    mma_tf32(c[mt][nt][0], c[mt][nt][1], c[mt][nt][2], c[mt][nt][3],
                             a0, a1, a2, a3, b0, b1);
                }
            }
        }
    }
}

// ================= mega0: all three layer-0 projections + counts in ONE launch =================
__global__ __launch_bounds__(256, 2) void mega0(const float* __restrict__ feats,
                                                const float* __restrict__ emb_card,
                                                const float* __restrict__ emb_merch,
                                                const float* __restrict__ W0,
                                                const float* __restrict__ b0,
                                                const int* __restrict__ ci,
                                                const int* __restrict__ mi) {
    extern __shared__ __align__(16) char smem[];
    float* bs = (float*)(smem + 110592);
    int* ciS = (int*)(smem + 110784);
    int* miS = (int*)(smem + 111808);
    const int tid = threadIdx.x, lane = tid & 31, wid = tid >> 5;
    const int gid = lane >> 2, tig = lane & 3;
    int b = blockIdx.x;

    if (b < GC_BLK + GM_BLK) {
        bool isM = b >= GC_BLK;
        int row0 = (isM ? (b - GC_BLK) : b) * 256;
        int nrows = isM ? NM : NC;
        const float* X = isM ? emb_merch : emb_card;
        const float* Wg = W0 + (isM ? 2048 : 0);
        const float* B = b0 + (isM ? 16 : 0);
        float* out = isM ? g_bufmA : g_bufcA;
        if (tid < 16) bs[tid] = B[tid];
        float c[2][2][4];
        mma_loop_256<2>(X, nrows, row0, Wg, smem, c);
#pragma unroll
        for (int mt = 0; mt < 2; mt++)
#pragma unroll
            for (int nt = 0; nt < 2; nt++) {
                int col = nt * 8 + 2 * tig;
                int r0_ = row0 + wid * 32 + mt * 16 + gid, r1_ = r0_ + 8;
                float bx = bs[col], by = bs[col + 1];
                if (r0_ < nrows)
                    *(float2*)(out + (size_t)r0_ * 16 + col) =
                        make_float2(c[mt][nt][0] + bx, c[mt][nt][1] + by);
                if (r1_ < nrows)
                    *(float2*)(out + (size_t)r1_ * 16 + col) =
                        make_float2(c[mt][nt][2] + bx, c[mt][nt][3] + by);
            }
    } else {
        int row0 = (b - GC_BLK - GM_BLK) * 256;
        if (tid < 48) bs[tid] = b0[32 + tid];
        {
            int row = row0 + tid;
            ciS[tid] = (row < NT) ? ci[row] : 0;
            miS[tid] = (row < NT) ? mi[row] : 0;
        }
        float c[2][6][4];
        mma_loop_256<6>(feats, NT, row0, W0 + 4096, smem, c);

        __syncthreads();                      // Xs dead; reuse as Cs[256][52]
        float* Cs = (float*)smem;
#pragma unroll
        for (int mt = 0; mt < 2; mt++)
#pragma unroll
            for (int nt = 0; nt < 6; nt++) {
                int ra = wid * 32 + mt * 16 + gid, rb = ra + 8, col = nt * 8 + 2 * tig;
                *(float2*)(Cs + ra * 52 + col) = make_float2(c[mt][nt][0], c[mt][nt][1]);
                *(float2*)(Cs + rb * 52 + col) = make_float2(c[mt][nt][2], c[mt][nt][3]);
            }
        __syncthreads();

        const int cg = tid & 3, rg = tid >> 2;
#pragma unroll
        for (int pass = 0; pass < 4; pass++) {
            int r = pass * 64 + rg, row = row0 + r;
            if (row < NT) {
                int cI = ciS[r], mI = miS[r];
#pragma unroll
                for (int u = 0; u < 3; u++) {
                    int q = cg * 12 + u * 4;
                    float4 v = *(const float4*)(Cs + r * 52 + q);
                    float vx = v.x + bs[q + 0], vy = v.y + bs[q + 1];
                    float vz = v.z + bs[q + 2], vw = v.w + bs[q + 3];
                    int e = q >> 4, j = q & 15;
                    if (e == 0)
                        *(float4*)(g_ht + (size_t)row * 16 + j) = make_float4(vx, vy, vz, vw);
                    else if (e == 1) {
                        red4(&g_sumcA[(size_t)cI * 16 + j], vx, vy, vz, vw);
                        if (q == 16) red1(&g_cntc[cI], 1.f);
                    } else {
                        red4(&g_summA[(size_t)mI * 16 + j], vx, vy, vz, vw);
                        if (q == 32) red1(&g_cntm[mI], 1.f);
                    }
                }
            }
        }
    }
}

// ================= mega1 (per-row): node + txn roles =================
// node block: thread = one node row; reads sumA/cnt, writes bufB
// txn block: 128 rows, 2 threads/row in the SAME warp (adjacent lanes -> gather dedup in L1);
//            reads g_ht, writes g_ht2 (no aliasing), scatters to sumB
__global__ __launch_bounds__(256) void mega1(const float* __restrict__ W1,
                                             const float* __restrict__ b1,
                                             const int* __restrict__ ci,
                                             const int* __restrict__ mi) {
    __shared__ float Ws[768];
    __shared__ float bs[48];
    const int tid = threadIdx.x;
    int b = blockIdx.x;

    if (b < NODE_BLK) {
        for (int i = tid; i < 512; i += 256) Ws[i] = W1[i];
        if (tid < 32) bs[tid] = b1[tid];
        __syncthreads();

        int gr = b * 256 + tid;
        if (gr < NC + NM) {
            bool isM = gr >= NC;
            int row = isM ? gr - NC : gr;
            const float4* S4 = (const float4*)(isM ? g_summA : g_sumcA);
            const float* cnt = isM ? g_cntm : g_cntc;
            float* out = isM ? g_bufmB : g_bufcB;
            const float* w = Ws + (isM ? 256 : 0);
            const float* bb = bs + (isM ? 16 : 0);

            float4 s0 = S4[(size_t)row * 4 + 0];
            float4 s1 = S4[(size_t)row * 4 + 1];
            float4 s2 = S4[(size_t)row * 4 + 2];
            float4 s3 = S4[(size_t)row * 4 + 3];
            float inv = 1.f / fmaxf(cnt[row], 1.f);
            float x[16] = {lrelu_f(s0.x * inv), lrelu_f(s0.y * inv), lrelu_f(s0.z * inv), lrelu_f(s0.w * inv),
                           lrelu_f(s1.x * inv), lrelu_f(s1.y * inv), lrelu_f(s1.z * inv), lrelu_f(s1.w * inv),
                           lrelu_f(s2.x * inv), lrelu_f(s2.y * inv), lrelu_f(s2.z * inv), lrelu_f(s2.w * inv),
                           lrelu_f(s3.x * inv), lrelu_f(s3.y * inv), lrelu_f(s3.z * inv), lrelu_f(s3.w * inv)};
            float acc[16];
#pragma unroll
            for (int c = 0; c < 16; c++) acc[c] = 0.f;
#pragma unroll
            for (int k = 0; k < 16; k++) {
                float xk = x[k];
#pragma unroll
                for (int c = 0; c < 16; c++) acc[c] += xk * w[k * 16 + c];
            }
#pragma unroll
            for (int p = 0; p < 4; p++)
                *(float4*)(out + (size_t)row * 16 + p * 4) =
                    make_float4(acc[p * 4 + 0] + bb[p * 4 + 0], acc[p * 4 + 1] + bb[p * 4 + 1],
                                acc[p * 4 + 2] + bb[p * 4 + 2], acc[p * 4 + 3] + bb[p * 4 + 3]);
        }
    } else {
        for (int i = tid; i < 768; i += 256) {
            int k = i / 48, cc = i % 48;
            Ws[i] = W1[512 + (cc >> 4) * 256 + k * 16 + (cc & 15)];
        }
        if (tid < 48) bs[tid] = b1[32 + tid];
        __syncthreads();

        int half = tid & 1;             // SAME-warp split: lanes 2r, 2r+1 share one row
        int r = tid >> 1;
        int row = (b - NODE_BLK) * 128 + r;
        if (row < NT) {
            int cI = ci[row], mI = mi[row];
            const float4* ht4 = (const float4*)g_ht;
            const float4* bc4 = (const float4*)g_bufcA;
            const float4* bm4 = (const float4*)g_bufmA;
            float x[16];
#pragma unroll
            for (int p = 0; p < 4; p++) {
                float4 a = ht4[(size_t)row * 4 + p];
                float4 gc = bc4[(size_t)cI * 4 + p];
                float4 gm = bm4[(size_t)mI * 4 + p];
                x[p * 4 + 0] = lrelu_f(a.x + gc.x + gm.x);
                x[p * 4 + 1] = lrelu_f(a.y + gc.y + gm.y);
                x[p * 4 + 2] = lrelu_f(a.z + gc.z + gm.z);
                x[p * 4 + 3] = lrelu_f(a.w + gc.w + gm.w);
            }
            int c0 = half * 24;
            float acc[24];
#pragma unroll
            for (int c = 0; c < 24; c++) acc[c] = 0.f;
#pragma unroll
            for (int k = 0; k < 16; k++) {
                float xk = x[k];
#pragma unroll
                for (int c = 0; c < 24; c++) acc[c] += xk * Ws[k * 48 + c0 + c];
            }
#pragma unroll
            for (int c = 0; c < 24; c++) acc[c] += bs[c0 + c];

            if (half == 0) {
#pragma unroll
                for (int p = 0; p < 4; p++)
                    *(float4*)(g_ht2 + (size_t)row * 16 + p * 4) =
                        make_float4(acc[p * 4], acc[p * 4 + 1], acc[p * 4 + 2], acc[p * 4 + 3]);
                red4(&g_sumcB[(size_t)cI * 16 + 0], acc[16], acc[17], acc[18], acc[19]);
                red4(&g_sumcB[(size_t)cI * 16 + 4], acc[20], acc[21], acc[22], acc[23]);
            } else {
                red4(&g_sumcB[(size_t)cI * 16 + 8], acc[0], acc[1], acc[2], acc[3]);
                red4(&g_sumcB[(size_t)cI * 16 + 12], acc[4], acc[5], acc[6], acc[7]);
                red4(&g_summB[(size_t)mI * 16 + 0], acc[8], acc[9], acc[10], acc[11]);
                red4(&g_summB[(size_t)mI * 16 + 4], acc[12], acc[13], acc[14], acc[15]);
                red4(&g_summB[(size_t)mI * 16 + 8], acc[16], acc[17], acc[18], acc[19]);
                red4(&g_summB[(size_t)mI * 16 + 12], acc[20], acc[21], acc[22], acc[23]);
            }
        }
    }
}

// ================= mega2 (per-row): layer-2 card/merch projections (reads sumB) =================
__global__ __launch_bounds__(256) void mega2(const float* __restrict__ W2,
                                             const float* __restrict__ b2) {
    __shared__ float Ws[512];
    __shared__ float bs[32];
    const int tid = threadIdx.x;
    for (int i = tid; i < 512; i += 256) Ws[i] = W2[i];
    if (tid < 32) bs[tid] = b2[tid];
    __syncthreads();

    int gr = blockIdx.x * 256 + tid;
    if (gr >= NC + NM) return;
    bool isM = gr >= NC;
    int row = isM ? gr - NC : gr;
    const float4* S4 = (const float4*)(isM ? g_summB : g_sumcB);
    const float* cnt = isM ? g_cntm : g_cntc;
    float* out = isM ? g_bufmA : g_bufcA;
    const float* w = Ws + (isM ? 256 : 0);
    const float* bb = bs + (isM ? 16 : 0);

    float4 s0 = S4[(size_t)row * 4 + 0];
    float4 s1 = S4[(size_t)row * 4 + 1];
    float4 s2 = S4[(size_t)row * 4 + 2];
    float4 s3 = S4[(size_t)row * 4 + 3];
    float inv = 1.f / fmaxf(cnt[row], 1.f);
    float x[16] = {lrelu_f(s0.x * inv), lrelu_f(s0.y * inv), lrelu_f(s0.z * inv), lrelu_f(s0.w * inv),
                   lrelu_f(s1.x * inv), lrelu_f(s1.y * inv), lrelu_f(s1.z * inv), lrelu_f(s1.w * inv),
                   lrelu_f(s2.x * inv), lrelu_f(s2.y * inv), lrelu_f(s2.z * inv), lrelu_f(s2.w * inv),
                   lrelu_f(s3.x * inv), lrelu_f(s3.y * inv), lrelu_f(s3.z * inv), lrelu_f(s3.w * inv)};
    float acc[16];
#pragma unroll
    for (int c = 0; c < 16; c++) acc[c] = 0.f;
#pragma unroll
    for (int k = 0; k < 16; k++) {
        float xk = x[k];
#pragma unroll
        for (int c = 0; c < 16; c++) acc[c] += xk * w[k * 16 + c];
    }
#pragma unroll
    for (int p = 0; p < 4; p++)
        *(float4*)(out + (size_t)row * 16 + p * 4) =
            make_float4(acc[p * 4 + 0] + bb[p * 4 + 0], acc[p * 4 + 1] + bb[p * 4 + 1],
                        acc[p * 4 + 2] + bb[p * 4 + 2], acc[p * 4 + 3] + bb[p * 4 + 3]);
}

// ================= ka_out (per-row) =================
__global__ __launch_bounds__(256) void ka_out_kernel(const float* __restrict__ W,
                                                     const float* __restrict__ B,
                                                     const int* __restrict__ ci,
                                                     const int* __restrict__ mi,
                                                     const float* __restrict__ Wout,
                                                     const float* __restrict__ Bout,
                                                     float* __restrict__ out) {
    __shared__ float Ws[256];
    __shared__ float bs[16];
    __shared__ float wo[32];
    const int tid = threadIdx.x;
    if (tid < 256) Ws[tid] = W[tid];
    if (tid < 16) bs[tid] = B[tid];
    if (tid < 32) wo[tid] = Wout[tid];
    __syncthreads();

    int row = blockIdx.x * 256 + tid;
    if (row >= NT) return;
    int cI = ci[row], mI = mi[row];

    const float4* ht4 = (const float4*)g_ht2;
    const float4* bcB = (const float4*)g_bufcB;
    const float4* bmB = (const float4*)g_bufmB;
    float x[16];
#pragma unroll
    for (int p = 0; p < 4; p++) {
        float4 a = ht4[(size_t)row * 4 + p];
        float4 gc = bcB[(size_t)cI * 4 + p];
        float4 gm = bmB[(size_t)mI * 4 + p];
        x[p * 4 + 0] = lrelu_f(a.x + gc.x + gm.x);
        x[p * 4 + 1] = lrelu_f(a.y + gc.y + gm.y);
        x[p * 4 + 2] = lrelu_f(a.z + gc.z + gm.z);
        x[p * 4 + 3] = lrelu_f(a.w + gc.w + gm.w);
    }
    float acc[16];
#pragma unroll
    for (int c = 0; c < 16; c++) acc[c] = 0.f;
#pragma unroll
    for (int k = 0; k < 16; k++) {
        float xk = x[k];
#pragma unroll
        for (int c = 0; c < 16; c++) acc[c] += xk * Ws[k * 16 + c];
    }

    const float4* bcA = (const float4*)g_bufcA;
    const float4* bmA = (const float4*)g_bufmA;
    float o0 = 0.f, o1 = 0.f;
#pragma unroll
    for (int p = 0; p < 4; p++) {
        float4 gc = bcA[(size_t)cI * 4 + p];
        float4 gm = bmA[(size_t)mI * 4 + p];
        float h0 = acc[p * 4 + 0] + bs[p * 4 + 0] + gc.x + gm.x;
        float h1 = acc[p * 4 + 1] + bs[p * 4 + 1] + gc.y + gm.y;
        float h2 = acc[p * 4 + 2] + bs[p * 4 + 2] + gc.z + gm.z;
        float h3 = acc[p * 4 + 3] + bs[p * 4 + 3] + gc.w + gm.w;
        o0 += h0 * wo[(p * 4 + 0) * 2] + h1 * wo[(p * 4 + 1) * 2]
            + h2 * wo[(p * 4 + 2) * 2] + h3 * wo[(p * 4 + 3) * 2];
        o1 += h0 * wo[(p * 4 + 0) * 2 + 1] + h1 * wo[(p * 4 + 1) * 2 + 1]
            + h2 * wo[(p * 4 + 2) * 2 + 1] + h3 * wo[(p * 4 + 3) * 2 + 1];
    }
    *(float2*)(out + (size_t)row * 2) = make_float2(o0 + Bout[0], o1 + Bout[1]);
}

// ---------------- launcher (mega1 is the 4th launch -> ncu capture slot) ----------------
extern "C" void kernel_launch(void* const* d_in, const int* in_sizes, int n_in,
                              void* d_out, int out_size) {
    (void)in_sizes; (void)n_in; (void)out_size;
    const float* feats     = (const float*)d_in[0];
    const float* emb_card  = (const float*)d_in[1];
    const float* emb_merch = (const float*)d_in[2];
    const float* W0        = (const float*)d_in[3];
    const float* b0        = (const float*)d_in[4];
    const float* W1        = (const float*)d_in[5];
    const float* b1        = (const float*)d_in[6];
    const float* W2        = (const float*)d_in[7];
    const float* b2        = (const float*)d_in[8];
    const float* Wout      = (const float*)d_in[9];
    const float* bout      = (const float*)d_in[10];
    const int*   ci        = (const int*)d_in[11];
    const int*   mi        = (const int*)d_in[12];
    float* out = (float*)d_out;

    const int G_ALL = GC_BLK + GM_BLK + GT_BLK;   // 6252

    static bool attr_set = false;
    if (!attr_set) {
        cudaFuncSetAttribute(mega0, cudaFuncAttributeMaxDynamicSharedMemorySize, M0_SMEM);
        attr_set = true;
    }

    zeroA_kernel<<<2048, 256>>>();                                                 // 1
    zeroBC_kernel<<<2048, 256>>>();                                                // 2
    mega0<<<G_ALL, 256, M0_SMEM>>>(feats, emb_card, emb_merch, W0, b0, ci, mi);    // 3
    mega1<<<NODE_BLK + TXN1_BLK, 256>>>(W1, b1, ci, mi);                           // 4 <- ncu
    mega2<<<NODE_BLK, 256>>>(W2, b2);
    ka_out_kernel<<<GT_BLK, 256>>>(W2 + 512, b2 + 32, ci, mi, Wout, bout, out);
}